// round 11
// baseline (speedup 1.0000x reference)
#include <cuda_runtime.h>
#include <math.h>

#define BATCH 32
#define SEQ   8192
#define DIM   256
#define CHUNKS 16
#define ROWS_PER_CHUNK (SEQ / CHUNKS)      // 512
#define WARPS_PER_BLOCK 8
#define ROWS_PER_WARP (ROWS_PER_CHUNK / WARPS_PER_BLOCK)  // 64
#define TOPK 5

// ---------------------------------------------------------------------------
// Eigen generic_fast_tanh_float (FMA path), as used by XLA-CPU for f32 tanh:
// input clamped to +/-7.99881172180175781, 7/4-term rational in x^2 evaluated
// with FMA (pmadd) Horner, IEEE divide, and |x| < 0.0004 -> x passthrough.
// All clamped inputs produce ONE identical float value -> exact tie structure
// matches the jax reference. Forced IEEE intrinsics so compiler flags can't
// perturb the bit pattern.
// ---------------------------------------------------------------------------
__device__ __forceinline__ float xla_tanhf(float x) {
    const float kLimit = 7.99881172180175781f;   // Eigen FMA-path clamp
    const float a1  = 4.89352455891786e-03f;
    const float a3  = 6.37261928875436e-04f;
    const float a5  = 1.48572235717979e-05f;
    const float a7  = 5.12229709037114e-08f;
    const float a9  = -8.60467152213735e-11f;
    const float a11 = 2.00018790482477e-13f;
    const float a13 = -2.76076847742355e-16f;
    const float b0  = 4.89352518554385e-03f;
    const float b2  = 2.26843463243900e-03f;
    const float b4  = 1.18534705686654e-04f;
    const float b6  = 1.19825839466702e-06f;

    float xc = fminf(fmaxf(x, -kLimit), kLimit);
    float x2 = __fmul_rn(xc, xc);
    float p;
    p = __fmaf_rn(x2, a13, a11);     // == pmadd(x2, alpha_13, alpha_11)
    p = __fmaf_rn(x2, p, a9);
    p = __fmaf_rn(x2, p, a7);
    p = __fmaf_rn(x2, p, a5);
    p = __fmaf_rn(x2, p, a3);
    p = __fmaf_rn(x2, p, a1);
    p = __fmul_rn(xc, p);
    float q;
    q = __fmaf_rn(x2, b6, b4);
    q = __fmaf_rn(x2, q, b2);
    q = __fmaf_rn(x2, q, b0);
    float r = __fdiv_rn(p, q);
    return (fabsf(x) < 0.0004f) ? x : r;
}

// Scratch (device globals — no allocation allowed in kernel_launch).
__device__ float g_et[BATCH * SEQ];                 // xla_tanh(x·W)
__device__ float g_colsum[BATCH * CHUNKS * DIM];    // per-chunk column sums (all rows)
__device__ float g_s1w[BATCH * CHUNKS * DIM];       // per-chunk sum (e^et - 1) * x over et >= T
__device__ float g_z1[BATCH * CHUNKS];              // per-chunk sum (e^et - 1)     over et >= T

// ---------------------------------------------------------------------------
// Pass 1: stream x once. Per (b, chunk) block:
//   - et[b,s] = xla_tanh(dot(x[b,s,:], W))
//   - colsum[d] = sum over chunk rows of x
//   - s1w[d], z1 = weight-exact sums over rows with et >= T (saturated set)
// ---------------------------------------------------------------------------
__global__ __launch_bounds__(256) void pass1_kernel(
    const float* __restrict__ x, const float* __restrict__ W)
{
    const int chunk = blockIdx.x;
    const int b     = blockIdx.y;
    const int tid   = threadIdx.x;
    const int wid   = tid >> 5;
    const int lane  = tid & 31;

    // Tie value shared by every clamped row (same constant through the same
    // instruction sequence as the reference).
    const float T = xla_tanhf(7.99881172180175781f);

    // Each lane owns 8 consecutive columns: [lane*8, lane*8+8)
    const float4 w0 = *reinterpret_cast<const float4*>(W + lane * 8);
    const float4 w1 = *reinterpret_cast<const float4*>(W + lane * 8 + 4);

    float4 c0 = make_float4(0.f, 0.f, 0.f, 0.f);
    float4 c1 = make_float4(0.f, 0.f, 0.f, 0.f);
    float4 s0 = make_float4(0.f, 0.f, 0.f, 0.f);
    float4 s1 = make_float4(0.f, 0.f, 0.f, 0.f);
    float z1_local = 0.f;   // identical in every lane of the warp

    const size_t row0 = (size_t)b * SEQ + (size_t)chunk * ROWS_PER_CHUNK
                      + (size_t)wid * ROWS_PER_WARP;
    const float* xb  = x + row0 * DIM;
    float*       etb = g_et + row0;

    for (int r = 0; r < ROWS_PER_WARP; r += 4) {
        float4 a0[4], a1[4];
        // Front-batched loads: 8 independent LDG.128 per thread (MLP)
        #pragma unroll
        for (int j = 0; j < 4; j++) {
            const float* row = xb + (size_t)(r + j) * DIM + lane * 8;
            a0[j] = *reinterpret_cast<const float4*>(row);
            a1[j] = *reinterpret_cast<const float4*>(row + 4);
        }

        float d[4];
        #pragma unroll
        for (int j = 0; j < 4; j++) {
            float4 p = a0[j], q = a1[j];
            d[j] = p.x * w0.x + p.y * w0.y + p.z * w0.z + p.w * w0.w
                 + q.x * w1.x + q.y * w1.y + q.z * w1.z + q.w * w1.w;
            c0.x += p.x; c0.y += p.y; c0.z += p.z; c0.w += p.w;
            c1.x += q.x; c1.y += q.y; c1.z += q.z; c1.w += q.w;
        }
        // Butterfly reduce: ALL lanes end with the identical full dot product
        #pragma unroll
        for (int j = 0; j < 4; j++) {
            #pragma unroll
            for (int off = 16; off > 0; off >>= 1)
                d[j] += __shfl_xor_sync(0xffffffffu, d[j], off);
        }

        #pragma unroll
        for (int j = 0; j < 4; j++) {
            const float t = xla_tanhf(d[j]);      // identical in every lane
            if (lane == 0) etb[r + j] = t;
            if (t >= T) {                         // saturated row
                const float w = expf(t) - 1.0f;   // weight delta vs uniform
                float4 p = a0[j], q = a1[j];
                s0.x += w * p.x; s0.y += w * p.y; s0.z += w * p.z; s0.w += w * p.w;
                s1.x += w * q.x; s1.y += w * q.y; s1.z += w * q.z; s1.w += w * q.w;
                z1_local += w;
            }
        }
    }

    // Cross-warp reductions via smem
    __shared__ float scol[WARPS_PER_BLOCK * DIM];
    __shared__ float ss1 [WARPS_PER_BLOCK * DIM];
    __shared__ float sz1 [WARPS_PER_BLOCK];
    {
        float* myc = scol + wid * DIM + lane * 8;
        *reinterpret_cast<float4*>(myc)     = c0;
        *reinterpret_cast<float4*>(myc + 4) = c1;
        float* mys = ss1 + wid * DIM + lane * 8;
        *reinterpret_cast<float4*>(mys)     = s0;
        *reinterpret_cast<float4*>(mys + 4) = s1;
        if (lane == 0) sz1[wid] = z1_local;
    }
    __syncthreads();

    float cs = 0.f, s1s = 0.f;
    #pragma unroll
    for (int w = 0; w < WARPS_PER_BLOCK; w++) {
        cs  += scol[w * DIM + tid];
        s1s += ss1 [w * DIM + tid];
    }
    const size_t pbase = ((size_t)b * CHUNKS + chunk) * DIM + tid;
    g_colsum[pbase] = cs;
    g_s1w[pbase]    = s1s;
    if (tid == 0) {
        float z = 0.f;
        #pragma unroll
        for (int w = 0; w < WARPS_PER_BLOCK; w++) z += sz1[w];
        g_z1[b * CHUNKS + chunk] = z;
    }
}

// ---------------------------------------------------------------------------
// Pass 2: per batch b (32 blocks, 256 threads):
//   A) exact 5th-largest of et[b,:] (duplicate-aware iterative block-max)
//   B) mid set = { thr <= v < T }  (nonempty only when <5 rows saturate
//      -> guaranteed tiny); gather (s, exp(v)-1)
//   C) Z = 8192 + z1 + zmid
//      out[b,d] = (colsum[d] + S1w[d] + sum_mid (e^v-1)*x[b,s,d]) / Z
// ---------------------------------------------------------------------------
__global__ __launch_bounds__(256) void pass2_kernel(
    const float* __restrict__ x, float* __restrict__ out)
{
    const int b    = blockIdx.x;
    const int tid  = threadIdx.x;
    const int wid  = tid >> 5;
    const int lane = tid & 31;

    const float T = xla_tanhf(7.99881172180175781f);

    // Load this thread's 32 strided et values into registers
    float v[32];
    #pragma unroll
    for (int i = 0; i < 32; i++)
        v[i] = g_et[(size_t)b * SEQ + i * 256 + tid];

    __shared__ float s_warp_f[8];
    __shared__ int   s_warp_i[8];
    __shared__ float s_bcast_f;
    __shared__ int   s_bcast_i;

    const float INF = __int_as_float(0x7f800000);
    float bound = INF;
    float thr = -INF;
    int remaining = TOPK;

    for (int iter = 0; iter < TOPK; iter++) {
        // block max over { v : v < bound }
        float m = -INF;
        #pragma unroll
        for (int i = 0; i < 32; i++)
            if (v[i] < bound) m = fmaxf(m, v[i]);
        #pragma unroll
        for (int off = 16; off > 0; off >>= 1)
            m = fmaxf(m, __shfl_xor_sync(0xffffffffu, m, off));
        if (lane == 0) s_warp_f[wid] = m;
        __syncthreads();
        if (tid == 0) {
            float mm = s_warp_f[0];
            #pragma unroll
            for (int w = 1; w < 8; w++) mm = fmaxf(mm, s_warp_f[w]);
            s_bcast_f = mm;
        }
        __syncthreads();
        const float m_blk = s_bcast_f;

        // block count of { v == m_blk }
        int c = 0;
        #pragma unroll
        for (int i = 0; i < 32; i++)
            if (v[i] == m_blk) c++;
        #pragma unroll
        for (int off = 16; off > 0; off >>= 1)
            c += __shfl_xor_sync(0xffffffffu, c, off);
        if (lane == 0) s_warp_i[wid] = c;
        __syncthreads();
        if (tid == 0) {
            int cc = 0;
            #pragma unroll
            for (int w = 0; w < 8; w++) cc += s_warp_i[w];
            s_bcast_i = cc;
        }
        __syncthreads();
        const int c_blk = s_bcast_i;

        if (c_blk >= remaining) { thr = m_blk; break; }
        remaining -= c_blk;
        bound = m_blk;
        __syncthreads();
    }
    // thr is uniform across the block

    // Phase B: gather "mid" kept entries: thr <= v < T.
    // Empty when thr == T (the normal case). Otherwise <5 rows saturate,
    // so |mid| ~ 5 + ties at thr (cap 64 is ample).
    __shared__ int   s_nkept;
    __shared__ int   s_kidx[64];
    __shared__ float s_kw[64];
    if (tid == 0) s_nkept = 0;
    __syncthreads();

    #pragma unroll
    for (int i = 0; i < 32; i++) {
        if (v[i] >= thr && v[i] < T) {
            int k = atomicAdd(&s_nkept, 1);
            if (k < 64) {
                s_kidx[k] = i * 256 + tid;        // sequence index s
                s_kw[k]   = expf(v[i]) - 1.0f;    // weight delta vs uniform
            }
        }
    }
    __syncthreads();

    const int nk = min(s_nkept, 64);
    float zmid = 0.f;
    for (int k = 0; k < nk; k++) zmid += s_kw[k];

    // Saturated-set weighted sums
    float z1 = 0.f;
    #pragma unroll
    for (int c = 0; c < CHUNKS; c++) z1 += g_z1[b * CHUNKS + c];

    float colsum = 0.f, s1sum = 0.f;
    #pragma unroll
    for (int c = 0; c < CHUNKS; c++) {
        const size_t pbase = ((size_t)b * CHUNKS + c) * DIM + tid;
        colsum += g_colsum[pbase];
        s1sum  += g_s1w[pbase];
    }

    const float inv_z = 1.0f / (8192.0f + z1 + zmid);

    float acc = colsum + s1sum;
    for (int k = 0; k < nk; k++) {
        const int s = s_kidx[k];
        acc += s_kw[k] * x[((size_t)b * SEQ + s) * DIM + tid];
    }

    out[b * DIM + tid] = acc * inv_z;
}

extern "C" void kernel_launch(void* const* d_in, const int* in_sizes, int n_in,
                              void* d_out, int out_size)
{
    const float* x = (const float*)d_in[0];   // (32, 8192, 256) f32
    const float* W = (const float*)d_in[1];   // (256, 1) f32
    float* out = (float*)d_out;               // (32, 256) f32

    dim3 grid1(CHUNKS, BATCH);
    pass1_kernel<<<grid1, 256>>>(x, W);
    pass2_kernel<<<BATCH, 256>>>(x, out);
}

// round 15
// speedup vs baseline: 1.1178x; 1.1178x over previous
#include <cuda_runtime.h>
#include <math.h>

#define BATCH 32
#define SEQ   8192
#define DIM   256
#define CHUNKS 64
#define ROWS_PER_CHUNK (SEQ / CHUNKS)      // 128
#define WARPS_PER_BLOCK 8
#define ROWS_PER_WARP (ROWS_PER_CHUNK / WARPS_PER_BLOCK)  // 16
#define RGROUP 8                           // rows per front-batched load group
#define TOPK 5

// ---------------------------------------------------------------------------
// Eigen generic_fast_tanh_float (FMA path), as used by XLA-CPU for f32 tanh:
// input clamped to +/-7.99881172180175781, rational in x^2 with FMA Horner,
// IEEE divide, |x| < 0.0004 -> x passthrough. All clamped inputs produce ONE
// identical float value T -> exact tie structure matches the jax reference.
// ---------------------------------------------------------------------------
__device__ __forceinline__ float xla_tanhf(float x) {
    const float kLimit = 7.99881172180175781f;   // Eigen FMA-path clamp
    const float a1  = 4.89352455891786e-03f;
    const float a3  = 6.37261928875436e-04f;
    const float a5  = 1.48572235717979e-05f;
    const float a7  = 5.12229709037114e-08f;
    const float a9  = -8.60467152213735e-11f;
    const float a11 = 2.00018790482477e-13f;
    const float a13 = -2.76076847742355e-16f;
    const float b0  = 4.89352518554385e-03f;
    const float b2  = 2.26843463243900e-03f;
    const float b4  = 1.18534705686654e-04f;
    const float b6  = 1.19825839466702e-06f;

    float xc = fminf(fmaxf(x, -kLimit), kLimit);
    float x2 = __fmul_rn(xc, xc);
    float p;
    p = __fmaf_rn(x2, a13, a11);
    p = __fmaf_rn(x2, p, a9);
    p = __fmaf_rn(x2, p, a7);
    p = __fmaf_rn(x2, p, a5);
    p = __fmaf_rn(x2, p, a3);
    p = __fmaf_rn(x2, p, a1);
    p = __fmul_rn(xc, p);
    float q;
    q = __fmaf_rn(x2, b6, b4);
    q = __fmaf_rn(x2, q, b2);
    q = __fmaf_rn(x2, q, b0);
    float r = __fdiv_rn(p, q);
    return (fabsf(x) < 0.0004f) ? x : r;
}

// Scratch (device globals — no allocation allowed in kernel_launch).
__device__ float g_et[BATCH * SEQ];                 // xla_tanh(x·W)   (fallback path)
__device__ float g_colsum[BATCH * CHUNKS * DIM];    // per-chunk column sums (all rows)
__device__ float g_s1w[BATCH * CHUNKS * DIM];       // per-chunk sum (e^et - 1)*x over et >= T
__device__ float g_z1[BATCH * CHUNKS];              // per-chunk sum (e^et - 1)   over et >= T
__device__ int   g_nge[BATCH * CHUNKS];             // per-chunk count et >= T
__device__ int   g_ngt[BATCH * CHUNKS];             // per-chunk count et >  T

// ---------------------------------------------------------------------------
// Pass 1: stream x once. Per (b, chunk) block (128 rows):
//   - et[b,s] = xla_tanh(dot(x[b,s,:], W))
//   - colsum[d] = sum over chunk rows of x
//   - s1w[d], z1, n_ge, n_gt over the saturated set {et >= T}
// 8-row groups: 16 front-batched LDG.128 per thread for deep MLP.
// ---------------------------------------------------------------------------
__global__ __launch_bounds__(256, 2) void pass1_kernel(
    const float* __restrict__ x, const float* __restrict__ W)
{
    const int chunk = blockIdx.x;
    const int b     = blockIdx.y;
    const int tid   = threadIdx.x;
    const int wid   = tid >> 5;
    const int lane  = tid & 31;

    // Tie value shared by every clamped row.
    const float T = xla_tanhf(7.99881172180175781f);

    // Each lane owns 8 consecutive columns: [lane*8, lane*8+8)
    const float4 w0 = *reinterpret_cast<const float4*>(W + lane * 8);
    const float4 w1 = *reinterpret_cast<const float4*>(W + lane * 8 + 4);

    float4 c0 = make_float4(0.f, 0.f, 0.f, 0.f);
    float4 c1 = make_float4(0.f, 0.f, 0.f, 0.f);
    float4 s0 = make_float4(0.f, 0.f, 0.f, 0.f);
    float4 s1 = make_float4(0.f, 0.f, 0.f, 0.f);
    float z1_local = 0.f;   // warp-uniform
    int   nge_local = 0;    // warp-uniform
    int   ngt_local = 0;    // warp-uniform

    const size_t row0 = (size_t)b * SEQ + (size_t)chunk * ROWS_PER_CHUNK
                      + (size_t)wid * ROWS_PER_WARP;
    const float* xb  = x + row0 * DIM;
    float*       etb = g_et + row0;

    #pragma unroll
    for (int r = 0; r < ROWS_PER_WARP; r += RGROUP) {
        float4 a0[RGROUP], a1[RGROUP];
        // Front-batched: 16 independent LDG.128 per thread
        #pragma unroll
        for (int j = 0; j < RGROUP; j++) {
            const float* row = xb + (size_t)(r + j) * DIM + lane * 8;
            a0[j] = *reinterpret_cast<const float4*>(row);
            a1[j] = *reinterpret_cast<const float4*>(row + 4);
        }

        float d[RGROUP];
        #pragma unroll
        for (int j = 0; j < RGROUP; j++) {
            float4 p = a0[j], q = a1[j];
            d[j] = p.x * w0.x + p.y * w0.y + p.z * w0.z + p.w * w0.w
                 + q.x * w1.x + q.y * w1.y + q.z * w1.z + q.w * w1.w;
            c0.x += p.x; c0.y += p.y; c0.z += p.z; c0.w += p.w;
            c1.x += q.x; c1.y += q.y; c1.z += q.z; c1.w += q.w;
        }
        // Butterfly reduce: ALL lanes end with the identical full dot product
        #pragma unroll
        for (int j = 0; j < RGROUP; j++) {
            #pragma unroll
            for (int off = 16; off > 0; off >>= 1)
                d[j] += __shfl_xor_sync(0xffffffffu, d[j], off);
        }

        #pragma unroll
        for (int j = 0; j < RGROUP; j++) {
            const float t = xla_tanhf(d[j]);      // identical in every lane
            if (lane == 0) etb[r + j] = t;
            if (t >= T) {                         // saturated row
                const float w = expf(t) - 1.0f;
                float4 p = a0[j], q = a1[j];
                s0.x += w * p.x; s0.y += w * p.y; s0.z += w * p.z; s0.w += w * p.w;
                s1.x += w * q.x; s1.y += w * q.y; s1.z += w * q.z; s1.w += w * q.w;
                z1_local += w;
                nge_local++;
                if (t > T) ngt_local++;
            }
        }
    }

    // Cross-warp reductions via smem
    __shared__ float scol[WARPS_PER_BLOCK * DIM];
    __shared__ float ss1 [WARPS_PER_BLOCK * DIM];
    __shared__ float sz1 [WARPS_PER_BLOCK];
    __shared__ int   snge[WARPS_PER_BLOCK];
    __shared__ int   sngt[WARPS_PER_BLOCK];
    {
        float* myc = scol + wid * DIM + lane * 8;
        *reinterpret_cast<float4*>(myc)     = c0;
        *reinterpret_cast<float4*>(myc + 4) = c1;
        float* mys = ss1 + wid * DIM + lane * 8;
        *reinterpret_cast<float4*>(mys)     = s0;
        *reinterpret_cast<float4*>(mys + 4) = s1;
        if (lane == 0) { sz1[wid] = z1_local; snge[wid] = nge_local; sngt[wid] = ngt_local; }
    }
    __syncthreads();

    float cs = 0.f, s1s = 0.f;
    #pragma unroll
    for (int w = 0; w < WARPS_PER_BLOCK; w++) {
        cs  += scol[w * DIM + tid];
        s1s += ss1 [w * DIM + tid];
    }
    const size_t pbase = ((size_t)b * CHUNKS + chunk) * DIM + tid;
    g_colsum[pbase] = cs;
    g_s1w[pbase]    = s1s;
    if (tid == 0) {
        float z = 0.f; int ng = 0, nt = 0;
        #pragma unroll
        for (int w = 0; w < WARPS_PER_BLOCK; w++) { z += sz1[w]; ng += snge[w]; nt += sngt[w]; }
        g_z1[b * CHUNKS + chunk]  = z;
        g_nge[b * CHUNKS + chunk] = ng;
        g_ngt[b * CHUNKS + chunk] = nt;
    }
}

// ---------------------------------------------------------------------------
// Pass 2: per batch b (32 blocks, 256 threads):
//   FAST PATH (n_gt==0 && n_ge>=5, the expected regime): thr == T provably,
//     mid set empty -> out[b,d] = (colsum[d] + S1w[d]) / (8192 + z1).
//   FALLBACK: full duplicate-aware 5th-largest over g_et + tiny mid gather.
// ---------------------------------------------------------------------------
__global__ __launch_bounds__(256) void pass2_kernel(
    const float* __restrict__ x, float* __restrict__ out)
{
    const int b    = blockIdx.x;
    const int tid  = threadIdx.x;
    const int wid  = tid >> 5;
    const int lane = tid & 31;

    const float T = xla_tanhf(7.99881172180175781f);

    // Totals over chunks (every thread computes the same values)
    int nge = 0, ngt = 0;
    #pragma unroll
    for (int c = 0; c < CHUNKS; c++) { nge += g_nge[b * CHUNKS + c]; ngt += g_ngt[b * CHUNKS + c]; }
    const bool fast = (ngt == 0) && (nge >= TOPK);

    __shared__ int   s_nkept;
    __shared__ int   s_kidx[64];
    __shared__ float s_kw[64];
    int nk = 0;

    if (!fast) {
        // ---- Full top-5 threshold over et (rare path) ----
        float v[32];
        #pragma unroll
        for (int i = 0; i < 32; i++)
            v[i] = g_et[(size_t)b * SEQ + i * 256 + tid];

        __shared__ float s_warp_f[8];
        __shared__ int   s_warp_i[8];
        __shared__ float s_bcast_f;
        __shared__ int   s_bcast_i;

        const float INF = __int_as_float(0x7f800000);
        float bound = INF;
        float thr = -INF;
        int remaining = TOPK;

        for (int iter = 0; iter < TOPK; iter++) {
            float m = -INF;
            #pragma unroll
            for (int i = 0; i < 32; i++)
                if (v[i] < bound) m = fmaxf(m, v[i]);
            #pragma unroll
            for (int off = 16; off > 0; off >>= 1)
                m = fmaxf(m, __shfl_xor_sync(0xffffffffu, m, off));
            if (lane == 0) s_warp_f[wid] = m;
            __syncthreads();
            if (tid == 0) {
                float mm = s_warp_f[0];
                #pragma unroll
                for (int w = 1; w < 8; w++) mm = fmaxf(mm, s_warp_f[w]);
                s_bcast_f = mm;
            }
            __syncthreads();
            const float m_blk = s_bcast_f;

            int c = 0;
            #pragma unroll
            for (int i = 0; i < 32; i++)
                if (v[i] == m_blk) c++;
            #pragma unroll
            for (int off = 16; off > 0; off >>= 1)
                c += __shfl_xor_sync(0xffffffffu, c, off);
            if (lane == 0) s_warp_i[wid] = c;
            __syncthreads();
            if (tid == 0) {
                int cc = 0;
                #pragma unroll
                for (int w = 0; w < 8; w++) cc += s_warp_i[w];
                s_bcast_i = cc;
            }
            __syncthreads();
            const int c_blk = s_bcast_i;

            if (c_blk >= remaining) { thr = m_blk; break; }
            remaining -= c_blk;
            bound = m_blk;
            __syncthreads();
        }

        // Gather "mid" kept entries: thr <= v < T  (tiny by construction)
        if (tid == 0) s_nkept = 0;
        __syncthreads();
        #pragma unroll
        for (int i = 0; i < 32; i++) {
            if (v[i] >= thr && v[i] < T) {
                int k = atomicAdd(&s_nkept, 1);
                if (k < 64) {
                    s_kidx[k] = i * 256 + tid;
                    s_kw[k]   = expf(v[i]) - 1.0f;
                }
            }
        }
        __syncthreads();
        nk = min(s_nkept, 64);
    }

    float zmid = 0.f;
    for (int k = 0; k < nk; k++) zmid += s_kw[k];

    float z1 = 0.f;
    #pragma unroll
    for (int c = 0; c < CHUNKS; c++) z1 += g_z1[b * CHUNKS + c];

    float colsum = 0.f, s1sum = 0.f;
    #pragma unroll
    for (int c = 0; c < CHUNKS; c++) {
        const size_t pbase = ((size_t)b * CHUNKS + c) * DIM + tid;
        colsum += g_colsum[pbase];
        s1sum  += g_s1w[pbase];
    }

    const float inv_z = 1.0f / (8192.0f + z1 + zmid);

    float acc = colsum + s1sum;
    for (int k = 0; k < nk; k++) {
        const int s = s_kidx[k];
        acc += s_kw[k] * x[((size_t)b * SEQ + s) * DIM + tid];
    }

    out[b * DIM + tid] = acc * inv_z;
}

extern "C" void kernel_launch(void* const* d_in, const int* in_sizes, int n_in,
                              void* d_out, int out_size)
{
    const float* x = (const float*)d_in[0];   // (32, 8192, 256) f32
    const float* W = (const float*)d_in[1];   // (256, 1) f32
    float* out = (float*)d_out;               // (32, 256) f32

    dim3 grid1(CHUNKS, BATCH);
    pass1_kernel<<<grid1, 256>>>(x, W);
    pass2_kernel<<<BATCH, 256>>>(x, out);
}

// round 17
// speedup vs baseline: 1.2185x; 1.0900x over previous
#include <cuda_runtime.h>
#include <math.h>

#define BATCH 32
#define SEQ   8192
#define DIM   256
#define CHUNKS 64
#define ROWS_PER_CHUNK (SEQ / CHUNKS)      // 128
#define WARPS_PER_BLOCK 8
#define ROWS_PER_WARP (ROWS_PER_CHUNK / WARPS_PER_BLOCK)  // 16
#define RGROUP 8                           // rows per front-batched load group
#define TOPK 5
#define CHUNKS_PER_WARP (CHUNKS / WARPS_PER_BLOCK)        // 8

// ---------------------------------------------------------------------------
// Eigen generic_fast_tanh_float (FMA path), as used by XLA-CPU for f32 tanh:
// input clamped to +/-7.99881172180175781, rational in x^2 with FMA Horner,
// IEEE divide, |x| < 0.0004 -> x passthrough. All clamped inputs produce ONE
// identical float value T -> exact tie structure matches the jax reference.
// ---------------------------------------------------------------------------
__device__ __forceinline__ float xla_tanhf(float x) {
    const float kLimit = 7.99881172180175781f;   // Eigen FMA-path clamp
    const float a1  = 4.89352455891786e-03f;
    const float a3  = 6.37261928875436e-04f;
    const float a5  = 1.48572235717979e-05f;
    const float a7  = 5.12229709037114e-08f;
    const float a9  = -8.60467152213735e-11f;
    const float a11 = 2.00018790482477e-13f;
    const float a13 = -2.76076847742355e-16f;
    const float b0  = 4.89352518554385e-03f;
    const float b2  = 2.26843463243900e-03f;
    const float b4  = 1.18534705686654e-04f;
    const float b6  = 1.19825839466702e-06f;

    float xc = fminf(fmaxf(x, -kLimit), kLimit);
    float x2 = __fmul_rn(xc, xc);
    float p;
    p = __fmaf_rn(x2, a13, a11);
    p = __fmaf_rn(x2, p, a9);
    p = __fmaf_rn(x2, p, a7);
    p = __fmaf_rn(x2, p, a5);
    p = __fmaf_rn(x2, p, a3);
    p = __fmaf_rn(x2, p, a1);
    p = __fmul_rn(xc, p);
    float q;
    q = __fmaf_rn(x2, b6, b4);
    q = __fmaf_rn(x2, q, b2);
    q = __fmaf_rn(x2, q, b0);
    float r = __fdiv_rn(p, q);
    return (fabsf(x) < 0.0004f) ? x : r;
}

// Scratch (device globals — no allocation allowed in kernel_launch).
__device__ float g_et[BATCH * SEQ];                 // xla_tanh(x·W)   (fallback path)
__device__ float g_colsum[BATCH * CHUNKS * DIM];    // per-chunk column sums (all rows)
__device__ float g_s1w[BATCH * CHUNKS * DIM];       // per-chunk sum (e^et - 1)*x over et >= T
__device__ float g_z1[BATCH * CHUNKS];              // per-chunk sum (e^et - 1)   over et >= T
__device__ int   g_nge[BATCH * CHUNKS];             // per-chunk count et >= T
__device__ int   g_ngt[BATCH * CHUNKS];             // per-chunk count et >  T

// ---------------------------------------------------------------------------
// Pass 1: stream x once (evict-first: __ldcs keeps partials L2-resident).
// Per (b, chunk) block (128 rows):
//   - et[b,s] = xla_tanh(dot(x[b,s,:], W))
//   - colsum[d] = sum over chunk rows of x
//   - s1w[d], z1, n_ge, n_gt over the saturated set {et >= T}
// ---------------------------------------------------------------------------
__global__ __launch_bounds__(256, 2) void pass1_kernel(
    const float* __restrict__ x, const float* __restrict__ W)
{
    const int chunk = blockIdx.x;
    const int b     = blockIdx.y;
    const int tid   = threadIdx.x;
    const int wid   = tid >> 5;
    const int lane  = tid & 31;

    // Tie value shared by every clamped row.
    const float T = xla_tanhf(7.99881172180175781f);

    // Each lane owns 8 consecutive columns: [lane*8, lane*8+8)
    const float4 w0 = *reinterpret_cast<const float4*>(W + lane * 8);
    const float4 w1 = *reinterpret_cast<const float4*>(W + lane * 8 + 4);

    float4 c0 = make_float4(0.f, 0.f, 0.f, 0.f);
    float4 c1 = make_float4(0.f, 0.f, 0.f, 0.f);
    float4 s0 = make_float4(0.f, 0.f, 0.f, 0.f);
    float4 s1 = make_float4(0.f, 0.f, 0.f, 0.f);
    float z1_local = 0.f;   // warp-uniform
    int   nge_local = 0;    // warp-uniform
    int   ngt_local = 0;    // warp-uniform

    const size_t row0 = (size_t)b * SEQ + (size_t)chunk * ROWS_PER_CHUNK
                      + (size_t)wid * ROWS_PER_WARP;
    const float* xb  = x + row0 * DIM;
    float*       etb = g_et + row0;

    #pragma unroll
    for (int r = 0; r < ROWS_PER_WARP; r += RGROUP) {
        float4 a0[RGROUP], a1[RGROUP];
        // Front-batched: 16 independent streaming LDG.128 per thread
        #pragma unroll
        for (int j = 0; j < RGROUP; j++) {
            const float* row = xb + (size_t)(r + j) * DIM + lane * 8;
            a0[j] = __ldcs(reinterpret_cast<const float4*>(row));
            a1[j] = __ldcs(reinterpret_cast<const float4*>(row + 4));
        }

        float d[RGROUP];
        #pragma unroll
        for (int j = 0; j < RGROUP; j++) {
            float4 p = a0[j], q = a1[j];
            d[j] = p.x * w0.x + p.y * w0.y + p.z * w0.z + p.w * w0.w
                 + q.x * w1.x + q.y * w1.y + q.z * w1.z + q.w * w1.w;
            c0.x += p.x; c0.y += p.y; c0.z += p.z; c0.w += p.w;
            c1.x += q.x; c1.y += q.y; c1.z += q.z; c1.w += q.w;
        }
        // Butterfly reduce: ALL lanes end with the identical full dot product
        #pragma unroll
        for (int j = 0; j < RGROUP; j++) {
            #pragma unroll
            for (int off = 16; off > 0; off >>= 1)
                d[j] += __shfl_xor_sync(0xffffffffu, d[j], off);
        }

        #pragma unroll
        for (int j = 0; j < RGROUP; j++) {
            const float t = xla_tanhf(d[j]);      // identical in every lane
            if (lane == 0) etb[r + j] = t;
            if (t >= T) {                         // saturated row
                const float w = expf(t) - 1.0f;
                float4 p = a0[j], q = a1[j];
                s0.x += w * p.x; s0.y += w * p.y; s0.z += w * p.z; s0.w += w * p.w;
                s1.x += w * q.x; s1.y += w * q.y; s1.z += w * q.z; s1.w += w * q.w;
                z1_local += w;
                nge_local++;
                if (t > T) ngt_local++;
            }
        }
    }

    // Cross-warp reductions via smem
    __shared__ float scol[WARPS_PER_BLOCK * DIM];
    __shared__ float ss1 [WARPS_PER_BLOCK * DIM];
    __shared__ float sz1 [WARPS_PER_BLOCK];
    __shared__ int   snge[WARPS_PER_BLOCK];
    __shared__ int   sngt[WARPS_PER_BLOCK];
    {
        float* myc = scol + wid * DIM + lane * 8;
        *reinterpret_cast<float4*>(myc)     = c0;
        *reinterpret_cast<float4*>(myc + 4) = c1;
        float* mys = ss1 + wid * DIM + lane * 8;
        *reinterpret_cast<float4*>(mys)     = s0;
        *reinterpret_cast<float4*>(mys + 4) = s1;
        if (lane == 0) { sz1[wid] = z1_local; snge[wid] = nge_local; sngt[wid] = ngt_local; }
    }
    __syncthreads();

    float cs = 0.f, s1s = 0.f;
    #pragma unroll
    for (int w = 0; w < WARPS_PER_BLOCK; w++) {
        cs  += scol[w * DIM + tid];
        s1s += ss1 [w * DIM + tid];
    }
    const size_t pbase = ((size_t)b * CHUNKS + chunk) * DIM + tid;
    g_colsum[pbase] = cs;
    g_s1w[pbase]    = s1s;
    if (tid == 0) {
        float z = 0.f; int ng = 0, nt = 0;
        #pragma unroll
        for (int w = 0; w < WARPS_PER_BLOCK; w++) { z += sz1[w]; ng += snge[w]; nt += sngt[w]; }
        g_z1[b * CHUNKS + chunk]  = z;
        g_nge[b * CHUNKS + chunk] = ng;
        g_ngt[b * CHUNKS + chunk] = nt;
    }
}

// ---------------------------------------------------------------------------
// Pass 2: per batch b (32 blocks, 256 threads).
//   Chunk combine: warp w owns chunks [8w, 8w+8); lane owns 8 dims.
//   Two front-batched groups of 16 LDG.128/thread -> smem cross-warp reduce.
//   FAST PATH (n_gt==0 && n_ge>=5): thr == T provably, mid set empty.
//   FALLBACK: full duplicate-aware 5th-largest over g_et + tiny mid gather.
// ---------------------------------------------------------------------------
__global__ __launch_bounds__(256) void pass2_kernel(
    const float* __restrict__ x, float* __restrict__ out)
{
    const int b    = blockIdx.x;
    const int tid  = threadIdx.x;
    const int wid  = tid >> 5;
    const int lane = tid & 31;

    const float T = xla_tanhf(7.99881172180175781f);

    // Stage meta (z1, nge, ngt) through smem once.
    __shared__ float sm_z1[CHUNKS];
    __shared__ int   sm_nge[CHUNKS];
    __shared__ int   sm_ngt[CHUNKS];
    if (tid < CHUNKS) {
        sm_z1[tid]  = g_z1[b * CHUNKS + tid];
        sm_nge[tid] = g_nge[b * CHUNKS + tid];
        sm_ngt[tid] = g_ngt[b * CHUNKS + tid];
    }
    __syncthreads();

    int nge = 0, ngt = 0;
    float z1 = 0.f;
    #pragma unroll
    for (int c = 0; c < CHUNKS; c++) { nge += sm_nge[c]; ngt += sm_ngt[c]; z1 += sm_z1[c]; }
    const bool fast = (ngt == 0) && (nge >= TOPK);

    // ---- Chunk combine with explicit MLP ----
    // Warp w covers chunks [8w, 8w+8); lane covers dims [lane*8, lane*8+8).
    float4 cc0 = make_float4(0.f,0.f,0.f,0.f), cc1 = make_float4(0.f,0.f,0.f,0.f);
    float4 sa0 = make_float4(0.f,0.f,0.f,0.f), sa1 = make_float4(0.f,0.f,0.f,0.f);
    {
        const size_t base = (size_t)b * CHUNKS * DIM;
        #pragma unroll
        for (int g = 0; g < 2; g++) {
            float4 tc[8], ts[8];
            // Front-batched: 16 independent LDG.128
            #pragma unroll
            for (int j = 0; j < 4; j++) {
                const int c = wid * CHUNKS_PER_WARP + g * 4 + j;
                const float* pc = g_colsum + base + (size_t)c * DIM + lane * 8;
                const float* ps = g_s1w    + base + (size_t)c * DIM + lane * 8;
                tc[j*2]   = *reinterpret_cast<const float4*>(pc);
                tc[j*2+1] = *reinterpret_cast<const float4*>(pc + 4);
                ts[j*2]   = *reinterpret_cast<const float4*>(ps);
                ts[j*2+1] = *reinterpret_cast<const float4*>(ps + 4);
            }
            #pragma unroll
            for (int j = 0; j < 4; j++) {
                cc0.x += tc[j*2].x;   cc0.y += tc[j*2].y;   cc0.z += tc[j*2].z;   cc0.w += tc[j*2].w;
                cc1.x += tc[j*2+1].x; cc1.y += tc[j*2+1].y; cc1.z += tc[j*2+1].z; cc1.w += tc[j*2+1].w;
                sa0.x += ts[j*2].x;   sa0.y += ts[j*2].y;   sa0.z += ts[j*2].z;   sa0.w += ts[j*2].w;
                sa1.x += ts[j*2+1].x; sa1.y += ts[j*2+1].y; sa1.z += ts[j*2+1].z; sa1.w += ts[j*2+1].w;
            }
        }
    }

    // Cross-warp reduction via smem (8 warp-partials per dim)
    __shared__ float scol[WARPS_PER_BLOCK * DIM];
    __shared__ float ss1 [WARPS_PER_BLOCK * DIM];
    {
        float* myc = scol + wid * DIM + lane * 8;
        *reinterpret_cast<float4*>(myc)     = cc0;
        *reinterpret_cast<float4*>(myc + 4) = cc1;
        float* mys = ss1 + wid * DIM + lane * 8;
        *reinterpret_cast<float4*>(mys)     = sa0;
        *reinterpret_cast<float4*>(mys + 4) = sa1;
    }
    __syncthreads();

    float colsum = 0.f, s1sum = 0.f;
    #pragma unroll
    for (int w = 0; w < WARPS_PER_BLOCK; w++) {
        colsum += scol[w * DIM + tid];
        s1sum  += ss1 [w * DIM + tid];
    }

    // ---- Threshold / mid gather (rare fallback) ----
    __shared__ int   s_nkept;
    __shared__ int   s_kidx[64];
    __shared__ float s_kw[64];
    int nk = 0;

    if (!fast) {
        float v[32];
        #pragma unroll
        for (int i = 0; i < 32; i++)
            v[i] = g_et[(size_t)b * SEQ + i * 256 + tid];

        __shared__ float s_warp_f[8];
        __shared__ int   s_warp_i[8];
        __shared__ float s_bcast_f;
        __shared__ int   s_bcast_i;

        const float INF = __int_as_float(0x7f800000);
        float bound = INF;
        float thr = -INF;
        int remaining = TOPK;

        for (int iter = 0; iter < TOPK; iter++) {
            float m = -INF;
            #pragma unroll
            for (int i = 0; i < 32; i++)
                if (v[i] < bound) m = fmaxf(m, v[i]);
            #pragma unroll
            for (int off = 16; off > 0; off >>= 1)
                m = fmaxf(m, __shfl_xor_sync(0xffffffffu, m, off));
            if (lane == 0) s_warp_f[wid] = m;
            __syncthreads();
            if (tid == 0) {
                float mm = s_warp_f[0];
                #pragma unroll
                for (int w = 1; w < 8; w++) mm = fmaxf(mm, s_warp_f[w]);
                s_bcast_f = mm;
            }
            __syncthreads();
            const float m_blk = s_bcast_f;

            int c = 0;
            #pragma unroll
            for (int i = 0; i < 32; i++)
                if (v[i] == m_blk) c++;
            #pragma unroll
            for (int off = 16; off > 0; off >>= 1)
                c += __shfl_xor_sync(0xffffffffu, c, off);
            if (lane == 0) s_warp_i[wid] = c;
            __syncthreads();
            if (tid == 0) {
                int cc = 0;
                #pragma unroll
                for (int w = 0; w < 8; w++) cc += s_warp_i[w];
                s_bcast_i = cc;
            }
            __syncthreads();
            const int c_blk = s_bcast_i;

            if (c_blk >= remaining) { thr = m_blk; break; }
            remaining -= c_blk;
            bound = m_blk;
            __syncthreads();
        }

        if (tid == 0) s_nkept = 0;
        __syncthreads();
        #pragma unroll
        for (int i = 0; i < 32; i++) {
            if (v[i] >= thr && v[i] < T) {
                int k = atomicAdd(&s_nkept, 1);
                if (k < 64) {
                    s_kidx[k] = i * 256 + tid;
                    s_kw[k]   = expf(v[i]) - 1.0f;
                }
            }
        }
        __syncthreads();
        nk = min(s_nkept, 64);
    }

    float zmid = 0.f;
    for (int k = 0; k < nk; k++) zmid += s_kw[k];

    const float inv_z = 1.0f / (8192.0f + z1 + zmid);

    float acc = colsum + s1sum;
    for (int k = 0; k < nk; k++) {
        const int s = s_kidx[k];
        acc += s_kw[k] * x[((size_t)b * SEQ + s) * DIM + tid];
    }

    out[b * DIM + tid] = acc * inv_z;
}

extern "C" void kernel_launch(void* const* d_in, const int* in_sizes, int n_in,
                              void* d_out, int out_size)
{
    const float* x = (const float*)d_in[0];   // (32, 8192, 256) f32
    const float* W = (const float*)d_in[1];   // (256, 1) f32
    float* out = (float*)d_out;               // (32, 256) f32

    dim3 grid1(CHUNKS, BATCH);
    pass1_kernel<<<grid1, 256>>>(x, W);
    pass2_kernel<<<BATCH, 256>>>(x, out);
}